// round 2
// baseline (speedup 1.0000x reference)
#include <cuda_runtime.h>
#include <cuda_bf16.h>

#define NV 100000
#define NE 1000000
#define D  64

// Scratch for verts @ W1^T + b1  (25.6 MB static device array — allocation-free)
__device__ float g_w1x[(size_t)NV * D];

// ---------------------------------------------------------------------------
// Kernel A: fused dual GEMM.
//   out[v][j]  = sum_k verts[v][k] * W0[j][k] + b0[j]
//   g_w1x[v][j]= sum_k verts[v][k] * W1[j][k] + b1[j]
// Weights transposed into smem (WT[k][j]) so LDS across j is conflict-free.
// blockDim = (64, 4): tx = output feature j, ty = row within group.
// ---------------------------------------------------------------------------
__global__ __launch_bounds__(256) void gemm_dual_kernel(
    const float* __restrict__ verts,
    const float* __restrict__ w0,
    const float* __restrict__ b0,
    const float* __restrict__ w1,
    const float* __restrict__ b1,
    float* __restrict__ out)
{
    __shared__ float w0t[D * D];
    __shared__ float w1t[D * D];

    const int tid = threadIdx.y * 64 + threadIdx.x;
    for (int i = tid; i < D * D; i += 256) {
        const int j = i / D;
        const int k = i % D;
        w0t[k * D + j] = w0[i];
        w1t[k * D + j] = w1[i];
    }
    __syncthreads();

    const int j = threadIdx.x;
    const float bias0 = b0[j];
    const float bias1 = b1[j];

    for (int row = blockIdx.x * 4 + threadIdx.y; row < NV; row += gridDim.x * 4) {
        const float4* vrow = reinterpret_cast<const float4*>(verts + (size_t)row * D);
        float acc0 = bias0;
        float acc1 = bias1;
#pragma unroll
        for (int k4 = 0; k4 < D / 4; k4++) {
            const float4 v = __ldg(vrow + k4);
            const int k = k4 * 4;
            acc0 = fmaf(v.x, w0t[(k + 0) * D + j], acc0);
            acc1 = fmaf(v.x, w1t[(k + 0) * D + j], acc1);
            acc0 = fmaf(v.y, w0t[(k + 1) * D + j], acc0);
            acc1 = fmaf(v.y, w1t[(k + 1) * D + j], acc1);
            acc0 = fmaf(v.z, w0t[(k + 2) * D + j], acc0);
            acc1 = fmaf(v.z, w1t[(k + 2) * D + j], acc1);
            acc0 = fmaf(v.w, w0t[(k + 3) * D + j], acc0);
            acc1 = fmaf(v.w, w1t[(k + 3) * D + j], acc1);
        }
        out[(size_t)row * D + j]    = acc0;
        g_w1x[(size_t)row * D + j]  = acc1;
    }
}

// ---------------------------------------------------------------------------
// Kernel B: undirected edge scatter with vector reductions.
// Thread t handles (edge e = t/16, chunk c = t%16): one float4 per direction.
//   out[a] += w1x[b];  out[b] += w1x[a]
// red.global.add.v4.f32 quarters the atomic instruction count vs scalar
// atomicAdd. 16 consecutive threads cover one 256B row -> coalesced gathers.
// Edges are int32 (JAX x64-disabled: jnp.int64 request silently yields int32).
// ---------------------------------------------------------------------------
__device__ __forceinline__ void red_add_v4(float* p, float4 v) {
    asm volatile("red.global.add.v4.f32 [%0], {%1, %2, %3, %4};"
                 :: "l"(p), "f"(v.x), "f"(v.y), "f"(v.z), "f"(v.w)
                 : "memory");
}

__global__ __launch_bounds__(256) void scatter_edges_kernel(
    const int* __restrict__ edges,
    float* __restrict__ out)
{
    const int idx = blockIdx.x * 256 + threadIdx.x;
    if (idx >= NE * 16) return;

    const int e = idx >> 4;
    const int c = (idx & 15) * 4;

    const int2 ab = __ldg(reinterpret_cast<const int2*>(edges) + e);
    const int a = ab.x;
    const int b = ab.y;

    const float4 va = *reinterpret_cast<const float4*>(g_w1x + (size_t)a * D + c);
    const float4 vb = *reinterpret_cast<const float4*>(g_w1x + (size_t)b * D + c);

    red_add_v4(out + (size_t)a * D + c, vb);
    red_add_v4(out + (size_t)b * D + c, va);
}

// ---------------------------------------------------------------------------
// Launch
// ---------------------------------------------------------------------------
extern "C" void kernel_launch(void* const* d_in, const int* in_sizes, int n_in,
                              void* d_out, int out_size)
{
    const float* verts = (const float*)d_in[0];
    const int*   edges = (const int*)d_in[1];
    const float* w0w   = (const float*)d_in[2];
    const float* w0b   = (const float*)d_in[3];
    const float* w1w   = (const float*)d_in[4];
    const float* w1b   = (const float*)d_in[5];
    float*       out   = (float*)d_out;

    dim3 gblock(64, 4, 1);
    gemm_dual_kernel<<<1024, gblock>>>(verts, w0w, w0b, w1w, w1b, out);

    const int nthreads = NE * 16;           // 16M threads, one float4-chunk each
    const int nblocks  = (nthreads + 255) / 256;
    scatter_edges_kernel<<<nblocks, 256>>>(edges, out);
}

// round 3
// speedup vs baseline: 1.5302x; 1.5302x over previous
#include <cuda_runtime.h>
#include <cuda_bf16.h>

#define NV 100000
#define NE 1000000
#define D  64

// Scratch for verts @ W1^T + b1  (25.6 MB static device array — allocation-free)
__device__ float g_w1x[(size_t)NV * D];

// ---------------------------------------------------------------------------
// Kernel A: dual GEMM as one register-blocked SGEMM.
//   C[v][0:64]   = verts[v] @ W0^T + b0   -> out
//   C[v][64:128] = verts[v] @ W1^T + b1   -> g_w1x
// CTA tile: 128 rows x 128 cols. 256 threads, each 8 rows x 8 cols in regs.
// As[k][row] (k-major) and Bs[k][col] -> 4x LDS.128 per 64 FFMA.
// K = 64, whole problem K-resident in smem; verts read exactly once.
// ---------------------------------------------------------------------------
__global__ __launch_bounds__(256) void gemm_dual_kernel(
    const float* __restrict__ verts,
    const float* __restrict__ w0,
    const float* __restrict__ b0,
    const float* __restrict__ w1,
    const float* __restrict__ b1,
    float* __restrict__ out)
{
    __shared__ float As[D * 128];   // As[k][row]  32KB
    __shared__ float Bs[D * 128];   // Bs[k][col]  32KB  (col<64: W0, col>=64: W1)

    const int t        = threadIdx.x;
    const int row_base = blockIdx.x * 128;

    // ---- fill Bs: Bs[k][j] = w0[j][k] ; Bs[k][64+j] = w1[j][k] -------------
    for (int i = t; i < D * D; i += 256) {
        const int j = i / D;         // output feature
        const int k = i % D;
        Bs[k * 128 + j]      = w0[i];
        Bs[k * 128 + 64 + j] = w1[i];
    }

    // ---- fill As (transposed): As[k][r] = verts[row_base+r][k] ------------
    // Thread handles float4s at (r = idx%128, k4 = idx/128); warp rows distinct
    // -> conflict-free scalar STS.
    for (int it = 0; it < 8; it++) {
        const int idx = it * 256 + t;          // 0..2047
        const int r   = idx & 127;
        const int k4  = idx >> 7;              // 0..15
        const int row = row_base + r;
        float4 v = make_float4(0.f, 0.f, 0.f, 0.f);
        if (row < NV)
            v = __ldg(reinterpret_cast<const float4*>(verts + (size_t)row * D) + k4);
        As[(k4 * 4 + 0) * 128 + r] = v.x;
        As[(k4 * 4 + 1) * 128 + r] = v.y;
        As[(k4 * 4 + 2) * 128 + r] = v.z;
        As[(k4 * 4 + 3) * 128 + r] = v.w;
    }
    __syncthreads();

    // ---- 8x8 register tile -------------------------------------------------
    const int tx = t & 15;           // col group: cols tx*8 .. tx*8+7
    const int ty = t >> 4;           // row group: rows ty*8 .. ty*8+7
    const int c0 = tx * 8;
    const int r0 = ty * 8;

    float acc[8][8];
    // bias init: cols 0-63 -> b0[c], cols 64-127 -> b1[c-64]
#pragma unroll
    for (int cc = 0; cc < 8; cc++) {
        const int c = c0 + cc;
        const float bias = (c < 64) ? __ldg(b0 + c) : __ldg(b1 + c - 64);
#pragma unroll
        for (int rr = 0; rr < 8; rr++) acc[rr][cc] = bias;
    }

#pragma unroll 8
    for (int k = 0; k < D; k++) {
        float a[8], b[8];
        *reinterpret_cast<float4*>(a)     = *reinterpret_cast<const float4*>(As + k * 128 + r0);
        *reinterpret_cast<float4*>(a + 4) = *reinterpret_cast<const float4*>(As + k * 128 + r0 + 4);
        *reinterpret_cast<float4*>(b)     = *reinterpret_cast<const float4*>(Bs + k * 128 + c0);
        *reinterpret_cast<float4*>(b + 4) = *reinterpret_cast<const float4*>(Bs + k * 128 + c0 + 4);
#pragma unroll
        for (int rr = 0; rr < 8; rr++)
#pragma unroll
            for (int cc = 0; cc < 8; cc++)
                acc[rr][cc] = fmaf(a[rr], b[cc], acc[rr][cc]);
    }

    // ---- epilogue: cols 0-63 -> out, 64-127 -> g_w1x ----------------------
    float* dst = (c0 < 64) ? out : g_w1x;
    const int cbase = c0 & 63;
#pragma unroll
    for (int rr = 0; rr < 8; rr++) {
        const int row = row_base + r0 + rr;
        if (row >= NV) break;
        float4 lo = make_float4(acc[rr][0], acc[rr][1], acc[rr][2], acc[rr][3]);
        float4 hi = make_float4(acc[rr][4], acc[rr][5], acc[rr][6], acc[rr][7]);
        float4* p = reinterpret_cast<float4*>(dst + (size_t)row * D + cbase);
        p[0] = lo;
        p[1] = hi;
    }
}

// ---------------------------------------------------------------------------
// Kernel B: undirected edge scatter with vector reductions (unchanged).
// ---------------------------------------------------------------------------
__device__ __forceinline__ void red_add_v4(float* p, float4 v) {
    asm volatile("red.global.add.v4.f32 [%0], {%1, %2, %3, %4};"
                 :: "l"(p), "f"(v.x), "f"(v.y), "f"(v.z), "f"(v.w)
                 : "memory");
}

__global__ __launch_bounds__(256) void scatter_edges_kernel(
    const int* __restrict__ edges,
    float* __restrict__ out)
{
    const int idx = blockIdx.x * 256 + threadIdx.x;
    if (idx >= NE * 16) return;

    const int e = idx >> 4;
    const int c = (idx & 15) * 4;

    const int2 ab = __ldg(reinterpret_cast<const int2*>(edges) + e);
    const int a = ab.x;
    const int b = ab.y;

    const float4 va = *reinterpret_cast<const float4*>(g_w1x + (size_t)a * D + c);
    const float4 vb = *reinterpret_cast<const float4*>(g_w1x + (size_t)b * D + c);

    red_add_v4(out + (size_t)a * D + c, vb);
    red_add_v4(out + (size_t)b * D + c, va);
}

// ---------------------------------------------------------------------------
// Launch
// ---------------------------------------------------------------------------
extern "C" void kernel_launch(void* const* d_in, const int* in_sizes, int n_in,
                              void* d_out, int out_size)
{
    const float* verts = (const float*)d_in[0];
    const int*   edges = (const int*)d_in[1];
    const float* w0w   = (const float*)d_in[2];
    const float* w0b   = (const float*)d_in[3];
    const float* w1w   = (const float*)d_in[4];
    const float* w1b   = (const float*)d_in[5];
    float*       out   = (float*)d_out;

    const int nblocks_g = (NV + 127) / 128;   // 782
    gemm_dual_kernel<<<nblocks_g, 256>>>(verts, w0w, w0b, w1w, w1b, out);

    const int nthreads = NE * 16;             // 16M threads, one float4-chunk each
    const int nblocks  = (nthreads + 255) / 256;
    scatter_edges_kernel<<<nblocks, 256>>>(edges, out);
}

// round 4
// speedup vs baseline: 1.6694x; 1.0910x over previous
#include <cuda_runtime.h>
#include <cuda_bf16.h>

#define NV 100000
#define NE 1000000
#define D  64

#define SCAN_BLK   512
#define NBLK_SCAN  ((NV + SCAN_BLK - 1) / SCAN_BLK)   // 196

// Static device scratch (no allocations allowed)
__device__ float g_w1x[(size_t)NV * D];   // verts @ W1^T + b1  (25.6 MB)
__device__ int   g_cur[NV];               // degree counts, then fill cursors
__device__ int   g_rs[NV + 1];            // CSR row starts
__device__ int   g_adj[2 * NE];           // adjacency (both directions)
__device__ int   g_bsum[256];             // scan block sums
__device__ int   g_boff[256];             // scan block offsets (exclusive)

// ---------------------------------------------------------------------------
// CSR build
// ---------------------------------------------------------------------------
__global__ void zero_deg_kernel() {
    const int i = blockIdx.x * 256 + threadIdx.x;
    if (i < NV) g_cur[i] = 0;
}

__global__ void degree_kernel(const int* __restrict__ edges) {
    const int e = blockIdx.x * 256 + threadIdx.x;
    if (e >= NE) return;
    const int2 ab = __ldg(reinterpret_cast<const int2*>(edges) + e);
    atomicAdd(&g_cur[ab.x], 1);
    atomicAdd(&g_cur[ab.y], 1);
}

// Per-block inclusive scan -> local exclusive prefix + block sum
__global__ __launch_bounds__(SCAN_BLK) void scan1_kernel() {
    __shared__ int s[SCAN_BLK];
    const int t = threadIdx.x;
    const int i = blockIdx.x * SCAN_BLK + t;
    const int v = (i < NV) ? g_cur[i] : 0;
    s[t] = v;
    __syncthreads();
#pragma unroll
    for (int off = 1; off < SCAN_BLK; off <<= 1) {
        const int x = (t >= off) ? s[t - off] : 0;
        __syncthreads();
        s[t] += x;
        __syncthreads();
    }
    if (i < NV) g_rs[i] = s[t] - v;                 // exclusive within block
    if (t == SCAN_BLK - 1) g_bsum[blockIdx.x] = s[t];
}

// Scan the (<=256) block sums
__global__ __launch_bounds__(256) void scan2_kernel() {
    __shared__ int s[256];
    const int t = threadIdx.x;
    const int v = (t < NBLK_SCAN) ? g_bsum[t] : 0;
    s[t] = v;
    __syncthreads();
#pragma unroll
    for (int off = 1; off < 256; off <<= 1) {
        const int x = (t >= off) ? s[t - off] : 0;
        __syncthreads();
        s[t] += x;
        __syncthreads();
    }
    g_boff[t] = s[t] - v;                           // exclusive
}

// Add block offsets; init fill cursors; close the row-start array
__global__ void scan3_kernel() {
    const int i = blockIdx.x * 256 + threadIdx.x;
    if (i >= NV) return;
    const int rs = g_rs[i] + g_boff[i / SCAN_BLK];
    g_rs[i]  = rs;
    g_cur[i] = rs;
    if (i == 0) g_rs[NV] = 2 * NE;
}

__global__ void fill_kernel(const int* __restrict__ edges) {
    const int e = blockIdx.x * 256 + threadIdx.x;
    if (e >= NE) return;
    const int2 ab = __ldg(reinterpret_cast<const int2*>(edges) + e);
    const int p1 = atomicAdd(&g_cur[ab.x], 1);
    g_adj[p1] = ab.y;
    const int p2 = atomicAdd(&g_cur[ab.y], 1);
    g_adj[p2] = ab.x;
}

// ---------------------------------------------------------------------------
// Dual GEMM as one register-blocked SGEMM.
//   C[v][0:64] -> out (verts@W0^T+b0),  C[v][64:128] -> g_w1x (verts@W1^T+b1)
// ---------------------------------------------------------------------------
__global__ __launch_bounds__(256) void gemm_dual_kernel(
    const float* __restrict__ verts,
    const float* __restrict__ w0,
    const float* __restrict__ b0,
    const float* __restrict__ w1,
    const float* __restrict__ b1,
    float* __restrict__ out)
{
    __shared__ float As[D * 128];
    __shared__ float Bs[D * 128];

    const int t        = threadIdx.x;
    const int row_base = blockIdx.x * 128;

    for (int i = t; i < D * D; i += 256) {
        const int j = i / D;
        const int k = i % D;
        Bs[k * 128 + j]      = w0[i];
        Bs[k * 128 + 64 + j] = w1[i];
    }

    for (int it = 0; it < 8; it++) {
        const int idx = it * 256 + t;
        const int r   = idx & 127;
        const int k4  = idx >> 7;
        const int row = row_base + r;
        float4 v = make_float4(0.f, 0.f, 0.f, 0.f);
        if (row < NV)
            v = __ldg(reinterpret_cast<const float4*>(verts + (size_t)row * D) + k4);
        As[(k4 * 4 + 0) * 128 + r] = v.x;
        As[(k4 * 4 + 1) * 128 + r] = v.y;
        As[(k4 * 4 + 2) * 128 + r] = v.z;
        As[(k4 * 4 + 3) * 128 + r] = v.w;
    }
    __syncthreads();

    const int tx = t & 15;
    const int ty = t >> 4;
    const int c0 = tx * 8;
    const int r0 = ty * 8;

    float acc[8][8];
#pragma unroll
    for (int cc = 0; cc < 8; cc++) {
        const int c = c0 + cc;
        const float bias = (c < 64) ? __ldg(b0 + c) : __ldg(b1 + c - 64);
#pragma unroll
        for (int rr = 0; rr < 8; rr++) acc[rr][cc] = bias;
    }

#pragma unroll 8
    for (int k = 0; k < D; k++) {
        float a[8], b[8];
        *reinterpret_cast<float4*>(a)     = *reinterpret_cast<const float4*>(As + k * 128 + r0);
        *reinterpret_cast<float4*>(a + 4) = *reinterpret_cast<const float4*>(As + k * 128 + r0 + 4);
        *reinterpret_cast<float4*>(b)     = *reinterpret_cast<const float4*>(Bs + k * 128 + c0);
        *reinterpret_cast<float4*>(b + 4) = *reinterpret_cast<const float4*>(Bs + k * 128 + c0 + 4);
#pragma unroll
        for (int rr = 0; rr < 8; rr++)
#pragma unroll
            for (int cc = 0; cc < 8; cc++)
                acc[rr][cc] = fmaf(a[rr], b[cc], acc[rr][cc]);
    }

    float* dst = (c0 < 64) ? out : g_w1x;
    const int cbase = c0 & 63;
#pragma unroll
    for (int rr = 0; rr < 8; rr++) {
        const int row = row_base + r0 + rr;
        if (row >= NV) break;
        float4 lo = make_float4(acc[rr][0], acc[rr][1], acc[rr][2], acc[rr][3]);
        float4 hi = make_float4(acc[rr][4], acc[rr][5], acc[rr][6], acc[rr][7]);
        float4* p = reinterpret_cast<float4*>(dst + (size_t)row * D + cbase);
        p[0] = lo;
        p[1] = hi;
    }
}

// ---------------------------------------------------------------------------
// CSR gather: out[v] += sum_{u in adj(v)} w1x[u]
// 16 threads per vertex, one float4 column-chunk each. No atomics.
// Neighbor rows unrolled x4 for MLP.
// ---------------------------------------------------------------------------
__global__ __launch_bounds__(256) void gather_kernel(float* __restrict__ out)
{
    const int t  = threadIdx.x;
    const int v  = blockIdx.x * 16 + (t >> 4);
    const int j4 = t & 15;
    if (v >= NV) return;

    const int rs = g_rs[v];
    const int re = g_rs[v + 1];

    float4 acc = make_float4(0.f, 0.f, 0.f, 0.f);
    int p = rs;
    for (; p + 4 <= re; p += 4) {
        const int u0 = __ldg(g_adj + p + 0);
        const int u1 = __ldg(g_adj + p + 1);
        const int u2 = __ldg(g_adj + p + 2);
        const int u3 = __ldg(g_adj + p + 3);
        const float4 x0 = reinterpret_cast<const float4*>(g_w1x + (size_t)u0 * D)[j4];
        const float4 x1 = reinterpret_cast<const float4*>(g_w1x + (size_t)u1 * D)[j4];
        const float4 x2 = reinterpret_cast<const float4*>(g_w1x + (size_t)u2 * D)[j4];
        const float4 x3 = reinterpret_cast<const float4*>(g_w1x + (size_t)u3 * D)[j4];
        acc.x += x0.x + x1.x + x2.x + x3.x;
        acc.y += x0.y + x1.y + x2.y + x3.y;
        acc.z += x0.z + x1.z + x2.z + x3.z;
        acc.w += x0.w + x1.w + x2.w + x3.w;
    }
    for (; p < re; p++) {
        const int u = __ldg(g_adj + p);
        const float4 x = reinterpret_cast<const float4*>(g_w1x + (size_t)u * D)[j4];
        acc.x += x.x; acc.y += x.y; acc.z += x.z; acc.w += x.w;
    }

    float4* o = reinterpret_cast<float4*>(out + (size_t)v * D) + j4;
    float4 c = *o;
    c.x += acc.x; c.y += acc.y; c.z += acc.z; c.w += acc.w;
    *o = c;
}

// ---------------------------------------------------------------------------
// Launch
// ---------------------------------------------------------------------------
extern "C" void kernel_launch(void* const* d_in, const int* in_sizes, int n_in,
                              void* d_out, int out_size)
{
    const float* verts = (const float*)d_in[0];
    const int*   edges = (const int*)d_in[1];
    const float* w0w   = (const float*)d_in[2];
    const float* w0b   = (const float*)d_in[3];
    const float* w1w   = (const float*)d_in[4];
    const float* w1b   = (const float*)d_in[5];
    float*       out   = (float*)d_out;

    const int nbV = (NV + 255) / 256;
    const int nbE = (NE + 255) / 256;

    // CSR build
    zero_deg_kernel<<<nbV, 256>>>();
    degree_kernel<<<nbE, 256>>>(edges);
    scan1_kernel<<<NBLK_SCAN, SCAN_BLK>>>();
    scan2_kernel<<<1, 256>>>();
    scan3_kernel<<<nbV, 256>>>();
    fill_kernel<<<nbE, 256>>>(edges);

    // GEMM (writes out = w0x, g_w1x = w1x)
    gemm_dual_kernel<<<(NV + 127) / 128, 256>>>(verts, w0w, w0b, w1w, w1b, out);

    // Pull-mode aggregation
    gather_kernel<<<(NV + 15) / 16, 256>>>(out);
}

// round 5
// speedup vs baseline: 1.8889x; 1.1315x over previous
#include <cuda_runtime.h>
#include <cuda_fp16.h>

#define NV 100000
#define NE 1000000
#define D  64

#define SCAN_BLK   512
#define NBLK_SCAN  ((NV + SCAN_BLK - 1) / SCAN_BLK)   // 196

__device__ __forceinline__ unsigned h2_as_uint(__half2 h) {
    return *reinterpret_cast<unsigned*>(&h);
}
__device__ __forceinline__ __half2 uint_as_h2(unsigned u) {
    return *reinterpret_cast<__half2*>(&u);
}

// Static device scratch (no allocations allowed)
__device__ __half g_w1x_h[(size_t)NV * D];  // verts @ W1^T + b1, fp16 (12.8 MB)
__device__ int    g_cur[NV];                // degree counts, then fill cursors
__device__ int    g_rs[NV + 1];             // CSR row starts
__device__ int    g_adj[2 * NE];            // adjacency (both directions)
__device__ int    g_bsum[NBLK_SCAN];        // scan block sums

// ---------------------------------------------------------------------------
__global__ void zero_deg_kernel() {
    const int i = blockIdx.x * 256 + threadIdx.x;
    if (i < NV) g_cur[i] = 0;
}

// ---------------------------------------------------------------------------
// Dual GEMM (register-blocked SGEMM) + fused degree histogram.
//   C[v][0:64] -> out (fp32, verts@W0^T+b0)
//   C[v][64:128] -> g_w1x_h (fp16, verts@W1^T+b1)
// Degree REDs are issued first; they drain asynchronously under the FMA work.
// ---------------------------------------------------------------------------
#define EDGES_PER_BLK 1280   // 782 blocks * 1280 >= NE

__global__ __launch_bounds__(256) void gemm_dual_deg_kernel(
    const float* __restrict__ verts,
    const int*   __restrict__ edges,
    const float* __restrict__ w0,
    const float* __restrict__ b0,
    const float* __restrict__ w1,
    const float* __restrict__ b1,
    float* __restrict__ out)
{
    __shared__ float As[D * 128];
    __shared__ float Bs[D * 128];

    const int t        = threadIdx.x;
    const int row_base = blockIdx.x * 128;

    // ---- fused degree histogram (fire-and-forget reductions) --------------
    {
        const int e0 = blockIdx.x * EDGES_PER_BLK;
#pragma unroll
        for (int it = 0; it < EDGES_PER_BLK / 256; it++) {
            const int e = e0 + it * 256 + t;
            if (e < NE) {
                const int2 ab = __ldg(reinterpret_cast<const int2*>(edges) + e);
                atomicAdd(&g_cur[ab.x], 1);
                atomicAdd(&g_cur[ab.y], 1);
            }
        }
    }

    // ---- fill Bs: Bs[k][j] = w0[j][k] ; Bs[k][64+j] = w1[j][k] ------------
    for (int i = t; i < D * D; i += 256) {
        const int j = i / D;
        const int k = i % D;
        Bs[k * 128 + j]      = w0[i];
        Bs[k * 128 + 64 + j] = w1[i];
    }

    // ---- fill As (transposed): As[k][r] = verts[row_base+r][k] ------------
    for (int it = 0; it < 8; it++) {
        const int idx = it * 256 + t;
        const int r   = idx & 127;
        const int k4  = idx >> 7;
        const int row = row_base + r;
        float4 v = make_float4(0.f, 0.f, 0.f, 0.f);
        if (row < NV)
            v = __ldg(reinterpret_cast<const float4*>(verts + (size_t)row * D) + k4);
        As[(k4 * 4 + 0) * 128 + r] = v.x;
        As[(k4 * 4 + 1) * 128 + r] = v.y;
        As[(k4 * 4 + 2) * 128 + r] = v.z;
        As[(k4 * 4 + 3) * 128 + r] = v.w;
    }
    __syncthreads();

    const int tx = t & 15;
    const int ty = t >> 4;
    const int c0 = tx * 8;
    const int r0 = ty * 8;

    float acc[8][8];
#pragma unroll
    for (int cc = 0; cc < 8; cc++) {
        const int c = c0 + cc;
        const float bias = (c < 64) ? __ldg(b0 + c) : __ldg(b1 + c - 64);
#pragma unroll
        for (int rr = 0; rr < 8; rr++) acc[rr][cc] = bias;
    }

#pragma unroll 8
    for (int k = 0; k < D; k++) {
        float a[8], b[8];
        *reinterpret_cast<float4*>(a)     = *reinterpret_cast<const float4*>(As + k * 128 + r0);
        *reinterpret_cast<float4*>(a + 4) = *reinterpret_cast<const float4*>(As + k * 128 + r0 + 4);
        *reinterpret_cast<float4*>(b)     = *reinterpret_cast<const float4*>(Bs + k * 128 + c0);
        *reinterpret_cast<float4*>(b + 4) = *reinterpret_cast<const float4*>(Bs + k * 128 + c0 + 4);
#pragma unroll
        for (int rr = 0; rr < 8; rr++)
#pragma unroll
            for (int cc = 0; cc < 8; cc++)
                acc[rr][cc] = fmaf(a[rr], b[cc], acc[rr][cc]);
    }

    // ---- epilogue: cols 0-63 -> out (fp32); cols 64-127 -> g_w1x_h (fp16) --
    if (c0 < 64) {
#pragma unroll
        for (int rr = 0; rr < 8; rr++) {
            const int row = row_base + r0 + rr;
            if (row >= NV) break;
            float4* p = reinterpret_cast<float4*>(out + (size_t)row * D + c0);
            p[0] = make_float4(acc[rr][0], acc[rr][1], acc[rr][2], acc[rr][3]);
            p[1] = make_float4(acc[rr][4], acc[rr][5], acc[rr][6], acc[rr][7]);
        }
    } else {
        const int cbase = c0 - 64;
#pragma unroll
        for (int rr = 0; rr < 8; rr++) {
            const int row = row_base + r0 + rr;
            if (row >= NV) break;
            uint4 pk;
            pk.x = h2_as_uint(__floats2half2_rn(acc[rr][0], acc[rr][1]));
            pk.y = h2_as_uint(__floats2half2_rn(acc[rr][2], acc[rr][3]));
            pk.z = h2_as_uint(__floats2half2_rn(acc[rr][4], acc[rr][5]));
            pk.w = h2_as_uint(__floats2half2_rn(acc[rr][6], acc[rr][7]));
            *reinterpret_cast<uint4*>(g_w1x_h + (size_t)row * D + cbase) = pk;
        }
    }
}

// ---------------------------------------------------------------------------
// CSR scan
// ---------------------------------------------------------------------------
__global__ __launch_bounds__(SCAN_BLK) void scan1_kernel() {
    __shared__ int s[SCAN_BLK];
    const int t = threadIdx.x;
    const int i = blockIdx.x * SCAN_BLK + t;
    const int v = (i < NV) ? g_cur[i] : 0;
    s[t] = v;
    __syncthreads();
#pragma unroll
    for (int off = 1; off < SCAN_BLK; off <<= 1) {
        const int x = (t >= off) ? s[t - off] : 0;
        __syncthreads();
        s[t] += x;
        __syncthreads();
    }
    if (i < NV) g_rs[i] = s[t] - v;                 // exclusive within block
    if (t == SCAN_BLK - 1) g_bsum[blockIdx.x] = s[t];
}

// Fused: each block re-scans the <=196 block sums in smem, then fixes up
// its slice of g_rs and initializes the fill cursors.
__global__ __launch_bounds__(256) void scan23_kernel() {
    __shared__ int s[256];
    __shared__ int boff[256];
    const int t = threadIdx.x;
    const int v = (t < NBLK_SCAN) ? g_bsum[t] : 0;
    s[t] = v;
    __syncthreads();
#pragma unroll
    for (int off = 1; off < 256; off <<= 1) {
        const int x = (t >= off) ? s[t - off] : 0;
        __syncthreads();
        s[t] += x;
        __syncthreads();
    }
    boff[t] = s[t] - v;                             // exclusive
    __syncthreads();

    const int i = blockIdx.x * 256 + t;
    if (i >= NV) return;
    const int rs = g_rs[i] + boff[i / SCAN_BLK];
    g_rs[i]  = rs;
    g_cur[i] = rs;
    if (i == 0) g_rs[NV] = 2 * NE;
}

__global__ void fill_kernel(const int* __restrict__ edges) {
    const int e = blockIdx.x * 256 + threadIdx.x;
    if (e >= NE) return;
    const int2 ab = __ldg(reinterpret_cast<const int2*>(edges) + e);
    const int p1 = atomicAdd(&g_cur[ab.x], 1);
    g_adj[p1] = ab.y;
    const int p2 = atomicAdd(&g_cur[ab.y], 1);
    g_adj[p2] = ab.x;
}

// ---------------------------------------------------------------------------
// CSR gather (fp16 rows, fp32 accumulate): out[v] += sum_{u} w1x[u]
// 8 threads per vertex, each owns a 16B chunk (8 halves) of the 128B row.
// ---------------------------------------------------------------------------
__global__ __launch_bounds__(256) void gather_kernel(float* __restrict__ out)
{
    const int t = threadIdx.x;
    const int v = blockIdx.x * 32 + (t >> 3);
    const int j = t & 7;                    // 16B chunk index
    if (v >= NV) return;

    const int rs = g_rs[v];
    const int re = g_rs[v + 1];

    float a0 = 0.f, a1 = 0.f, a2 = 0.f, a3 = 0.f;
    float a4 = 0.f, a5 = 0.f, a6 = 0.f, a7 = 0.f;

#define ACC_ROW(u)                                                              \
    {                                                                           \
        const uint4 pk = __ldg(reinterpret_cast<const uint4*>(                  \
                                   g_w1x_h + (size_t)(u) * D) + j);             \
        const float2 f0 = __half22float2(uint_as_h2(pk.x));                     \
        const float2 f1 = __half22float2(uint_as_h2(pk.y));                     \
        const float2 f2 = __half22float2(uint_as_h2(pk.z));                     \
        const float2 f3 = __half22float2(uint_as_h2(pk.w));                     \
        a0 += f0.x; a1 += f0.y; a2 += f1.x; a3 += f1.y;                         \
        a4 += f2.x; a5 += f2.y; a6 += f3.x; a7 += f3.y;                         \
    }

    int p = rs;
    for (; p + 4 <= re; p += 4) {
        const int u0 = __ldg(g_adj + p + 0);
        const int u1 = __ldg(g_adj + p + 1);
        const int u2 = __ldg(g_adj + p + 2);
        const int u3 = __ldg(g_adj + p + 3);
        ACC_ROW(u0); ACC_ROW(u1); ACC_ROW(u2); ACC_ROW(u3);
    }
    for (; p < re; p++) {
        const int u = __ldg(g_adj + p);
        ACC_ROW(u);
    }
#undef ACC_ROW

    float4* o = reinterpret_cast<float4*>(out + (size_t)v * D + j * 8);
    float4 c0 = o[0], c1 = o[1];
    c0.x += a0; c0.y += a1; c0.z += a2; c0.w += a3;
    c1.x += a4; c1.y += a5; c1.z += a6; c1.w += a7;
    o[0] = c0;
    o[1] = c1;
}

// ---------------------------------------------------------------------------
// Launch
// ---------------------------------------------------------------------------
extern "C" void kernel_launch(void* const* d_in, const int* in_sizes, int n_in,
                              void* d_out, int out_size)
{
    const float* verts = (const float*)d_in[0];
    const int*   edges = (const int*)d_in[1];
    const float* w0w   = (const float*)d_in[2];
    const float* w0b   = (const float*)d_in[3];
    const float* w1w   = (const float*)d_in[4];
    const float* w1b   = (const float*)d_in[5];
    float*       out   = (float*)d_out;

    const int nbV = (NV + 255) / 256;
    const int nbE = (NE + 255) / 256;

    zero_deg_kernel<<<nbV, 256>>>();
    gemm_dual_deg_kernel<<<(NV + 127) / 128, 256>>>(verts, edges, w0w, w0b, w1w, w1b, out);
    scan1_kernel<<<NBLK_SCAN, SCAN_BLK>>>();
    scan23_kernel<<<nbV, 256>>>();
    fill_kernel<<<nbE, 256>>>(edges);
    gather_kernel<<<(NV + 31) / 32, 256>>>(out);
}

// round 6
// speedup vs baseline: 1.8955x; 1.0035x over previous
#include <cuda_runtime.h>
#include <cuda_fp16.h>

#define NV 100000
#define NE 1000000
#define D  64

#define SCAN_BLK   512
#define NBLK_SCAN  ((NV + SCAN_BLK - 1) / SCAN_BLK)   // 196

typedef unsigned long long u64;

__device__ __forceinline__ unsigned h2_as_uint(__half2 h) {
    return *reinterpret_cast<unsigned*>(&h);
}
__device__ __forceinline__ __half2 uint_as_h2(unsigned u) {
    return *reinterpret_cast<__half2*>(&u);
}
__device__ __forceinline__ u64 pack2(float lo, float hi) {
    u64 r;
    asm("mov.b64 %0, {%1, %2};" : "=l"(r) : "f"(lo), "f"(hi));
    return r;
}
__device__ __forceinline__ void unpack2(float& lo, float& hi, u64 v) {
    asm("mov.b64 {%0, %1}, %2;" : "=f"(lo), "=f"(hi) : "l"(v));
}
__device__ __forceinline__ u64 fma2(u64 a, u64 b, u64 c) {
    u64 d;
    asm("fma.rn.f32x2 %0, %1, %2, %3;" : "=l"(d) : "l"(a), "l"(b), "l"(c));
    return d;
}

// Static device scratch (no allocations allowed)
__device__ __half g_w1x_h[(size_t)NV * D];  // verts @ W1^T + b1, fp16 (12.8 MB)
__device__ int    g_cur[NV];                // degree counts, then fill cursors
__device__ int    g_rs[NV + 1];             // CSR row starts
__device__ int    g_adj[2 * NE];            // adjacency (both directions)
__device__ int    g_bsum[NBLK_SCAN];        // scan block sums

// ---------------------------------------------------------------------------
__global__ void zero_deg_kernel() {
    const int i = blockIdx.x * 256 + threadIdx.x;
    if (i < NV) g_cur[i] = 0;
}

// ---------------------------------------------------------------------------
// Dual GEMM with packed f32x2 FMAs (FFMA2) + fused degree histogram.
//   C[v][0:64] -> out (fp32, verts@W0^T+b0)
//   C[v][64:128] -> g_w1x_h (fp16, verts@W1^T+b1)
// Accumulators hold ROW-PAIRS packed in 64-bit regs: acc2[rr2][cc] =
// { C[r0+2rr2][c], C[r0+2rr2+1][c] }. The a-operand (row pair) loads straight
// from As as a u64 (consecutive rows are adjacent floats); only b needs a
// {b,b} dup-pack (ALU pipe, overlaps FMA pipe).
// ---------------------------------------------------------------------------
#define EDGES_PER_BLK 1280   // 782 blocks * 1280 >= NE

__global__ __launch_bounds__(256) void gemm_dual_deg_kernel(
    const float* __restrict__ verts,
    const int*   __restrict__ edges,
    const float* __restrict__ w0,
    const float* __restrict__ b0,
    const float* __restrict__ w1,
    const float* __restrict__ b1,
    float* __restrict__ out)
{
    __shared__ float As[D * 128];   // As[k][row]
    __shared__ float Bs[D * 128];   // Bs[k][col]

    const int t        = threadIdx.x;
    const int row_base = blockIdx.x * 128;

    // ---- fused degree histogram (fire-and-forget reductions) --------------
    {
        const int e0 = blockIdx.x * EDGES_PER_BLK;
#pragma unroll
        for (int it = 0; it < EDGES_PER_BLK / 256; it++) {
            const int e = e0 + it * 256 + t;
            if (e < NE) {
                const int2 ab = __ldg(reinterpret_cast<const int2*>(edges) + e);
                atomicAdd(&g_cur[ab.x], 1);
                atomicAdd(&g_cur[ab.y], 1);
            }
        }
    }

    // ---- fill Bs: Bs[k][j] = w0[j][k] ; Bs[k][64+j] = w1[j][k] ------------
    for (int i = t; i < D * D; i += 256) {
        const int j = i / D;
        const int k = i % D;
        Bs[k * 128 + j]      = w0[i];
        Bs[k * 128 + 64 + j] = w1[i];
    }

    // ---- fill As (transposed): As[k][r] = verts[row_base+r][k] ------------
    for (int it = 0; it < 8; it++) {
        const int idx = it * 256 + t;
        const int r   = idx & 127;
        const int k4  = idx >> 7;
        const int row = row_base + r;
        float4 v = make_float4(0.f, 0.f, 0.f, 0.f);
        if (row < NV)
            v = __ldg(reinterpret_cast<const float4*>(verts + (size_t)row * D) + k4);
        As[(k4 * 4 + 0) * 128 + r] = v.x;
        As[(k4 * 4 + 1) * 128 + r] = v.y;
        As[(k4 * 4 + 2) * 128 + r] = v.z;
        As[(k4 * 4 + 3) * 128 + r] = v.w;
    }
    __syncthreads();

    const int tx = t & 15;           // col group: cols c0 .. c0+7
    const int ty = t >> 4;           // row group: rows r0 .. r0+7
    const int c0 = tx * 8;
    const int r0 = ty * 8;

    u64 acc2[4][8];                  // [row-pair][col]
#pragma unroll
    for (int cc = 0; cc < 8; cc++) {
        const int c = c0 + cc;
        const float bias = (c < 64) ? __ldg(b0 + c) : __ldg(b1 + c - 64);
        const u64 bp = pack2(bias, bias);
#pragma unroll
        for (int rr2 = 0; rr2 < 4; rr2++) acc2[rr2][cc] = bp;
    }

#pragma unroll 4
    for (int k = 0; k < D; k++) {
        // a row-pairs: 4 x u64, straight from smem (16B-aligned)
        u64 ar[4];
        *reinterpret_cast<ulonglong2*>(ar)     =
            *reinterpret_cast<const ulonglong2*>(As + k * 128 + r0);
        *reinterpret_cast<ulonglong2*>(ar + 2) =
            *reinterpret_cast<const ulonglong2*>(As + k * 128 + r0 + 4);

        // b columns + dup-packs
        float bv[8];
        *reinterpret_cast<float4*>(bv)     = *reinterpret_cast<const float4*>(Bs + k * 128 + c0);
        *reinterpret_cast<float4*>(bv + 4) = *reinterpret_cast<const float4*>(Bs + k * 128 + c0 + 4);
        u64 bd[8];
#pragma unroll
        for (int cc = 0; cc < 8; cc++) bd[cc] = pack2(bv[cc], bv[cc]);

#pragma unroll
        for (int rr2 = 0; rr2 < 4; rr2++)
#pragma unroll
            for (int cc = 0; cc < 8; cc++)
                acc2[rr2][cc] = fma2(ar[rr2], bd[cc], acc2[rr2][cc]);
    }

    // ---- epilogue: cols 0-63 -> out (fp32); cols 64-127 -> g_w1x_h (fp16) --
#pragma unroll
    for (int rr2 = 0; rr2 < 4; rr2++) {
        float lo[8], hi[8];
#pragma unroll
        for (int cc = 0; cc < 8; cc++) unpack2(lo[cc], hi[cc], acc2[rr2][cc]);

        const int row_e = row_base + r0 + 2 * rr2;
        const int row_o = row_e + 1;

        if (c0 < 64) {
            if (row_e < NV) {
                float4* p = reinterpret_cast<float4*>(out + (size_t)row_e * D + c0);
                p[0] = make_float4(lo[0], lo[1], lo[2], lo[3]);
                p[1] = make_float4(lo[4], lo[5], lo[6], lo[7]);
            }
            if (row_o < NV) {
                float4* p = reinterpret_cast<float4*>(out + (size_t)row_o * D + c0);
                p[0] = make_float4(hi[0], hi[1], hi[2], hi[3]);
                p[1] = make_float4(hi[4], hi[5], hi[6], hi[7]);
            }
        } else {
            const int cbase = c0 - 64;
            if (row_e < NV) {
                uint4 pk;
                pk.x = h2_as_uint(__floats2half2_rn(lo[0], lo[1]));
                pk.y = h2_as_uint(__floats2half2_rn(lo[2], lo[3]));
                pk.z = h2_as_uint(__floats2half2_rn(lo[4], lo[5]));
                pk.w = h2_as_uint(__floats2half2_rn(lo[6], lo[7]));
                *reinterpret_cast<uint4*>(g_w1x_h + (size_t)row_e * D + cbase) = pk;
            }
            if (row_o < NV) {
                uint4 pk;
                pk.x = h2_as_uint(__floats2half2_rn(hi[0], hi[1]));
                pk.y = h2_as_uint(__floats2half2_rn(hi[2], hi[3]));
                pk.z = h2_as_uint(__floats2half2_rn(hi[4], hi[5]));
                pk.w = h2_as_uint(__floats2half2_rn(hi[6], hi[7]));
                *reinterpret_cast<uint4*>(g_w1x_h + (size_t)row_o * D + cbase) = pk;
            }
        }
    }
}

// ---------------------------------------------------------------------------
// CSR scan
// ---------------------------------------------------------------------------
__global__ __launch_bounds__(SCAN_BLK) void scan1_kernel() {
    __shared__ int s[SCAN_BLK];
    const int t = threadIdx.x;
    const int i = blockIdx.x * SCAN_BLK + t;
    const int v = (i < NV) ? g_cur[i] : 0;
    s[t] = v;
    __syncthreads();
#pragma unroll
    for (int off = 1; off < SCAN_BLK; off <<= 1) {
        const int x = (t >= off) ? s[t - off] : 0;
        __syncthreads();
        s[t] += x;
        __syncthreads();
    }
    if (i < NV) g_rs[i] = s[t] - v;                 // exclusive within block
    if (t == SCAN_BLK - 1) g_bsum[blockIdx.x] = s[t];
}

// Fused: each block re-scans the <=196 block sums in smem, then fixes up
// its slice of g_rs and initializes the fill cursors.
__global__ __launch_bounds__(256) void scan23_kernel() {
    __shared__ int s[256];
    __shared__ int boff[256];
    const int t = threadIdx.x;
    const int v = (t < NBLK_SCAN) ? g_bsum[t] : 0;
    s[t] = v;
    __syncthreads();
#pragma unroll
    for (int off = 1; off < 256; off <<= 1) {
        const int x = (t >= off) ? s[t - off] : 0;
        __syncthreads();
        s[t] += x;
        __syncthreads();
    }
    boff[t] = s[t] - v;                             // exclusive
    __syncthreads();

    const int i = blockIdx.x * 256 + t;
    if (i >= NV) return;
    const int rs = g_rs[i] + boff[i / SCAN_BLK];
    g_rs[i]  = rs;
    g_cur[i] = rs;
    if (i == 0) g_rs[NV] = 2 * NE;
}

__global__ void fill_kernel(const int* __restrict__ edges) {
    const int e = blockIdx.x * 256 + threadIdx.x;
    if (e >= NE) return;
    const int2 ab = __ldg(reinterpret_cast<const int2*>(edges) + e);
    const int p1 = atomicAdd(&g_cur[ab.x], 1);
    g_adj[p1] = ab.y;
    const int p2 = atomicAdd(&g_cur[ab.y], 1);
    g_adj[p2] = ab.x;
}

// ---------------------------------------------------------------------------
// CSR gather (fp16 rows, fp32 accumulate): out[v] += sum_{u} w1x[u]
// 8 threads per vertex, each owns a 16B chunk (8 halves) of the 128B row.
// ---------------------------------------------------------------------------
__global__ __launch_bounds__(256) void gather_kernel(float* __restrict__ out)
{
    const int t = threadIdx.x;
    const int v = blockIdx.x * 32 + (t >> 3);
    const int j = t & 7;                    // 16B chunk index
    if (v >= NV) return;

    const int rs = g_rs[v];
    const int re = g_rs[v + 1];

    float a0 = 0.f, a1 = 0.f, a2 = 0.f, a3 = 0.f;
    float a4 = 0.f, a5 = 0.f, a6 = 0.f, a7 = 0.f;

#define ACC_ROW(u)                                                              \
    {                                                                           \
        const uint4 pk = __ldg(reinterpret_cast<const uint4*>(                  \
                                   g_w1x_h + (size_t)(u) * D) + j);             \
        const float2 f0 = __half22float2(uint_as_h2(pk.x));                     \
        const float2 f1 = __half22float2(uint_as_h2(pk.y));                     \
        const float2 f2 = __half22float2(uint_as_h2(pk.z));                     \
        const float2 f3 = __half22float2(uint_as_h2(pk.w));                     \
        a0 += f0.x; a1 += f0.y; a2 += f1.x; a3 += f1.y;                         \
        a4 += f2.x; a5 += f2.y; a6 += f3.x; a7 += f3.y;                         \
    }

    int p = rs;
    for (; p + 4 <= re; p += 4) {
        const int u0 = __ldg(g_adj + p + 0);
        const int u1 = __ldg(g_adj + p + 1);
        const int u2 = __ldg(g_adj + p + 2);
        const int u3 = __ldg(g_adj + p + 3);
        ACC_ROW(u0); ACC_ROW(u1); ACC_ROW(u2); ACC_ROW(u3);
    }
    for (; p < re; p++) {
        const int u = __ldg(g_adj + p);
        ACC_ROW(u);
    }
#undef ACC_ROW

    float4* o = reinterpret_cast<float4*>(out + (size_t)v * D + j * 8);
    float4 c0 = o[0], c1 = o[1];
    c0.x += a0; c0.y += a1; c0.z += a2; c0.w += a3;
    c1.x += a4; c1.y += a5; c1.z += a6; c1.w += a7;
    o[0] = c0;
    o[1] = c1;
}

// ---------------------------------------------------------------------------
// Launch
// ---------------------------------------------------------------------------
extern "C" void kernel_launch(void* const* d_in, const int* in_sizes, int n_in,
                              void* d_out, int out_size)
{
    const float* verts = (const float*)d_in[0];
    const int*   edges = (const int*)d_in[1];
    const float* w0w   = (const float*)d_in[2];
    const float* w0b   = (const float*)d_in[3];
    const float* w1w   = (const float*)d_in[4];
    const float* w1b   = (const float*)d_in[5];
    float*       out   = (float*)d_out;

    const int nbV = (NV + 255) / 256;
    const int nbE = (NE + 255) / 256;

    zero_deg_kernel<<<nbV, 256>>>();
    gemm_dual_deg_kernel<<<(NV + 127) / 128, 256>>>(verts, edges, w0w, w0b, w1w, w1b, out);
    scan1_kernel<<<NBLK_SCAN, SCAN_BLK>>>();
    scan23_kernel<<<nbV, 256>>>();
    fill_kernel<<<nbE, 256>>>(edges);
    gather_kernel<<<(NV + 31) / 32, 256>>>(out);
}

// round 7
// speedup vs baseline: 2.8850x; 1.5220x over previous
#include <cuda_runtime.h>
#include <cuda_fp16.h>

#define NV 100000
#define NE 1000000
#define D  64

#define SCAN_BLK   512
#define NBLK_SCAN  ((NV + SCAN_BLK - 1) / SCAN_BLK)   // 196

#define AS_STRIDE 80   // halves per smem row (160B, 16B-aligned, conflict-free)

__device__ __forceinline__ unsigned h2_as_uint(__half2 h) {
    return *reinterpret_cast<unsigned*>(&h);
}
__device__ __forceinline__ __half2 uint_as_h2(unsigned u) {
    return *reinterpret_cast<__half2*>(&u);
}
__device__ __forceinline__ void ldsm_x4(unsigned& r0, unsigned& r1,
                                        unsigned& r2, unsigned& r3,
                                        unsigned addr) {
    asm volatile("ldmatrix.sync.aligned.m8n8.x4.shared.b16 {%0,%1,%2,%3}, [%4];"
                 : "=r"(r0), "=r"(r1), "=r"(r2), "=r"(r3) : "r"(addr));
}
__device__ __forceinline__ void mma16816(float* d, const unsigned* a,
                                         const unsigned* b) {
    asm volatile(
        "mma.sync.aligned.m16n8k16.row.col.f32.f16.f16.f32 "
        "{%0,%1,%2,%3}, {%4,%5,%6,%7}, {%8,%9}, {%0,%1,%2,%3};"
        : "+f"(d[0]), "+f"(d[1]), "+f"(d[2]), "+f"(d[3])
        : "r"(a[0]), "r"(a[1]), "r"(a[2]), "r"(a[3]), "r"(b[0]), "r"(b[1]));
}

// Static device scratch (no allocations allowed)
__device__ __half g_w1x_h[(size_t)NV * D];  // verts @ W1^T + b1, fp16 (12.8 MB)
__device__ int    g_cur[NV];                // degree counts, then fill cursors
__device__ int    g_rs[NV + 1];             // CSR row starts
__device__ int    g_adj[2 * NE];            // adjacency (both directions)
__device__ int    g_bsum[NBLK_SCAN];        // scan block sums

// ---------------------------------------------------------------------------
__global__ void zero_deg_kernel() {
    const int i = blockIdx.x * 256 + threadIdx.x;
    if (i < NV) g_cur[i] = 0;
}

// ---------------------------------------------------------------------------
// Tensor-core dual GEMM (fp16 HMMA, fp32 accum) + fused degree histogram.
//   C[v][0:64]  -> out     (fp32, verts@W0^T + b0)
//   C[v][64:128]-> g_w1x_h (fp16, verts@W1^T + b1)
// CTA: 128 rows x 128 cols, 8 warps in a 4x2 grid, warp tile 32x64,
// built from m16n8k16 fragments (2 m-tiles x 8 n-tiles x 4 k-chunks).
// Smem tiles use padded stride 80 halves for conflict-free ldmatrix.
// ---------------------------------------------------------------------------
#define EDGES_PER_BLK 1280   // 782 blocks * 1280 >= NE

__global__ __launch_bounds__(256) void gemm_dual_deg_kernel(
    const float* __restrict__ verts,
    const int*   __restrict__ edges,
    const float* __restrict__ w0,
    const float* __restrict__ b0,
    const float* __restrict__ w1,
    const float* __restrict__ b1,
    float* __restrict__ out)
{
    __shared__ __half As[128 * AS_STRIDE];   // As[row][k]  20KB
    __shared__ __half Bs[128 * AS_STRIDE];   // Bs[n][k]    20KB (n<64:W0, n>=64:W1)

    const int t        = threadIdx.x;
    const int row_base = blockIdx.x * 128;

    // ---- fused degree histogram (fire-and-forget reductions) --------------
    {
        const int e0 = blockIdx.x * EDGES_PER_BLK;
#pragma unroll
        for (int it = 0; it < EDGES_PER_BLK / 256; it++) {
            const int e = e0 + it * 256 + t;
            if (e < NE) {
                const int2 ab = __ldg(reinterpret_cast<const int2*>(edges) + e);
                atomicAdd(&g_cur[ab.x], 1);
                atomicAdd(&g_cur[ab.y], 1);
            }
        }
    }

    // ---- fill Bs: Bs[j][k] = w0[j][k]; Bs[64+j][k] = w1[j][k] (fp16) ------
    for (int i = t; i < 64 * 16; i += 256) {          // 1024 float4s each
        const int j  = i / 16;
        const int k4 = i % 16;
        const float4 v0 = __ldg(reinterpret_cast<const float4*>(w0) + i);
        const float4 v1 = __ldg(reinterpret_cast<const float4*>(w1) + i);
        uint2 p0, p1;
        p0.x = h2_as_uint(__floats2half2_rn(v0.x, v0.y));
        p0.y = h2_as_uint(__floats2half2_rn(v0.z, v0.w));
        p1.x = h2_as_uint(__floats2half2_rn(v1.x, v1.y));
        p1.y = h2_as_uint(__floats2half2_rn(v1.z, v1.w));
        *reinterpret_cast<uint2*>(Bs + j * AS_STRIDE + k4 * 4)        = p0;
        *reinterpret_cast<uint2*>(Bs + (64 + j) * AS_STRIDE + k4 * 4) = p1;
    }

    // ---- fill As: As[r][k] = verts[row_base+r][k] (fp16) ------------------
#pragma unroll
    for (int it = 0; it < 8; it++) {
        const int idx = it * 256 + t;                 // 0..2047
        const int r   = idx / 16;
        const int k4  = idx % 16;
        const int row = row_base + r;
        float4 v = make_float4(0.f, 0.f, 0.f, 0.f);
        if (row < NV)
            v = __ldg(reinterpret_cast<const float4*>(verts + (size_t)row * D) + k4);
        uint2 pk;
        pk.x = h2_as_uint(__floats2half2_rn(v.x, v.y));
        pk.y = h2_as_uint(__floats2half2_rn(v.z, v.w));
        *reinterpret_cast<uint2*>(As + r * AS_STRIDE + k4 * 4) = pk;
    }

    const int lane = t & 31;
    const int wid  = t >> 5;
    const int wr   = wid >> 1;         // warp row 0..3 -> m offset wr*32
    const int wc   = wid & 1;          // warp col 0..1 -> n offset wc*64
    const int cq   = (lane & 3) * 2;   // fragment col pair within 8-col tile
    const int rq   = lane >> 2;        // fragment row within 8-row group

    float acc[2][8][4];
#pragma unroll
    for (int nt = 0; nt < 8; nt++) {
        const int col = wc * 64 + nt * 8 + cq;
        float be, bo;
        if (col < 64) { be = __ldg(b0 + col);      bo = __ldg(b0 + col + 1); }
        else          { be = __ldg(b1 + col - 64); bo = __ldg(b1 + col - 63); }
#pragma unroll
        for (int mt = 0; mt < 2; mt++) {
            acc[mt][nt][0] = be; acc[mt][nt][1] = bo;
            acc[mt][nt][2] = be; acc[mt][nt][3] = bo;
        }
    }
    __syncthreads();

#pragma unroll
    for (int kc = 0; kc < 4; kc++) {
        const int k = kc * 16;

        unsigned a[2][4];
#pragma unroll
        for (int mt = 0; mt < 2; mt++) {
            const __half* p = As + (wr * 32 + mt * 16 + (lane & 15)) * AS_STRIDE
                                 + k + (lane >> 4) * 8;
            ldsm_x4(a[mt][0], a[mt][1], a[mt][2], a[mt][3],
                    (unsigned)__cvta_generic_to_shared(p));
        }

        unsigned b[8][2];
#pragma unroll
        for (int ntp = 0; ntp < 4; ntp++) {
            const int n0     = wc * 64 + ntp * 16;
            const int group  = lane >> 3;
            const int within = lane & 7;
            const __half* p = Bs + (n0 + within + (group >> 1) * 8) * AS_STRIDE
                                 + k + (group & 1) * 8;
            unsigned r0, r1, r2, r3;
            ldsm_x4(r0, r1, r2, r3, (unsigned)__cvta_generic_to_shared(p));
            b[2 * ntp][0]     = r0;  b[2 * ntp][1]     = r1;
            b[2 * ntp + 1][0] = r2;  b[2 * ntp + 1][1] = r3;
        }

#pragma unroll
        for (int mt = 0; mt < 2; mt++)
#pragma unroll
            for (int nt = 0; nt < 8; nt++)
                mma16816(acc[mt][nt], a[mt], b[nt]);
    }

    // ---- epilogue: fragment-direct stores ---------------------------------
#pragma unroll
    for (int mt = 0; mt < 2; mt++) {
        const int rbase = wr * 32 + mt * 16;
#pragma unroll
        for (int h = 0; h < 2; h++) {
            const int r = row_base + rbase + rq + h * 8;
            if (r >= NV) continue;
#pragma unroll
            for (int nt = 0; nt < 8; nt++) {
                const int col = wc * 64 + nt * 8 + cq;
                const float e = acc[mt][nt][h * 2 + 0];
                const float o = acc[mt][nt][h * 2 + 1];
                if (col < 64) {
                    *reinterpret_cast<float2*>(out + (size_t)r * D + col) =
                        make_float2(e, o);
                } else {
                    *reinterpret_cast<__half2*>(g_w1x_h + (size_t)r * D + col - 64) =
                        __floats2half2_rn(e, o);
                }
            }
        }
    }
}

// ---------------------------------------------------------------------------
// CSR scan
// ---------------------------------------------------------------------------
__global__ __launch_bounds__(SCAN_BLK) void scan1_kernel() {
    __shared__ int s[SCAN_BLK];
    const int t = threadIdx.x;
    const int i = blockIdx.x * SCAN_BLK + t;
    const int v = (i < NV) ? g_cur[i] : 0;
    s[t] = v;
    __syncthreads();
#pragma unroll
    for (int off = 1; off < SCAN_BLK; off <<= 1) {
        const int x = (t >= off) ? s[t - off] : 0;
        __syncthreads();
        s[t] += x;
        __syncthreads();
    }
    if (i < NV) g_rs[i] = s[t] - v;                 // exclusive within block
    if (t == SCAN_BLK - 1) g_bsum[blockIdx.x] = s[t];
}

// Fused: each block re-scans the <=196 block sums in smem, then fixes up
// its slice of g_rs and initializes the fill cursors.
__global__ __launch_bounds__(256) void scan23_kernel() {
    __shared__ int s[256];
    __shared__ int boff[256];
    const int t = threadIdx.x;
    const int v = (t < NBLK_SCAN) ? g_bsum[t] : 0;
    s[t] = v;
    __syncthreads();
#pragma unroll
    for (int off = 1; off < 256; off <<= 1) {
        const int x = (t >= off) ? s[t - off] : 0;
        __syncthreads();
        s[t] += x;
        __syncthreads();
    }
    boff[t] = s[t] - v;                             // exclusive
    __syncthreads();

    const int i = blockIdx.x * 256 + t;
    if (i >= NV) return;
    const int rs = g_rs[i] + boff[i / SCAN_BLK];
    g_rs[i]  = rs;
    g_cur[i] = rs;
    if (i == 0) g_rs[NV] = 2 * NE;
}

__global__ void fill_kernel(const int* __restrict__ edges) {
    const int e = blockIdx.x * 256 + threadIdx.x;
    if (e >= NE) return;
    const int2 ab = __ldg(reinterpret_cast<const int2*>(edges) + e);
    const int p1 = atomicAdd(&g_cur[ab.x], 1);
    g_adj[p1] = ab.y;
    const int p2 = atomicAdd(&g_cur[ab.y], 1);
    g_adj[p2] = ab.x;
}

// ---------------------------------------------------------------------------
// CSR gather (fp16 rows, fp32 accumulate): out[v] += sum_{u} w1x[u]
// 8 threads per vertex, each owns a 16B chunk (8 halves) of the 128B row.
// ---------------------------------------------------------------------------
__global__ __launch_bounds__(256) void gather_kernel(float* __restrict__ out)
{
    const int t = threadIdx.x;
    const int v = blockIdx.x * 32 + (t >> 3);
    const int j = t & 7;                    // 16B chunk index
    if (v >= NV) return;

    const int rs = g_rs[v];
    const int re = g_rs[v + 1];

    float a0 = 0.f, a1 = 0.f, a2 = 0.f, a3 = 0.f;
    float a4 = 0.f, a5 = 0.f, a6 = 0.f, a7 = 0.f;

#define ACC_ROW(u)                                                              \
    {                                                                           \
        const uint4 pk = __ldg(reinterpret_cast<const uint4*>(                  \
                                   g_w1x_h + (size_t)(u) * D) + j);             \
        const float2 f0 = __half22float2(uint_as_h2(pk.x));                     \
        const float2 f1 = __half22float2(uint_as_h2(pk.y));                     \
        const float2 f2 = __half22float2(uint_as_h2(pk.z));                     \
        const float2 f3 = __half22float2(uint_as_h2(pk.w));                     \
        a0 += f0.x; a1 += f0.y; a2 += f1.x; a3 += f1.y;                         \
        a4 += f2.x; a5 += f2.y; a6 += f3.x; a7 += f3.y;                         \
    }

    int p = rs;
    for (; p + 4 <= re; p += 4) {
        const int u0 = __ldg(g_adj + p + 0);
        const int u1 = __ldg(g_adj + p + 1);
        const int u2 = __ldg(g_adj + p + 2);
        const int u3 = __ldg(g_adj + p + 3);
        ACC_ROW(u0); ACC_ROW(u1); ACC_ROW(u2); ACC_ROW(u3);
    }
    for (; p < re; p++) {
        const int u = __ldg(g_adj + p);
        ACC_ROW(u);
    }
#undef ACC_ROW

    float4* o = reinterpret_cast<float4*>(out + (size_t)v * D + j * 8);
    float4 c0 = o[0], c1 = o[1];
    c0.x += a0; c0.y += a1; c0.z += a2; c0.w += a3;
    c1.x += a4; c1.y += a5; c1.z += a6; c1.w += a7;
    o[0] = c0;
    o[1] = c1;
}

// ---------------------------------------------------------------------------
// Launch
// ---------------------------------------------------------------------------
extern "C" void kernel_launch(void* const* d_in, const int* in_sizes, int n_in,
                              void* d_out, int out_size)
{
    const float* verts = (const float*)d_in[0];
    const int*   edges = (const int*)d_in[1];
    const float* w0w   = (const float*)d_in[2];
    const float* w0b   = (const float*)d_in[3];
    const float* w1w   = (const float*)d_in[4];
    const float* w1b   = (const float*)d_in[5];
    float*       out   = (float*)d_out;

    const int nbV = (NV + 255) / 256;
    const int nbE = (NE + 255) / 256;

    zero_deg_kernel<<<nbV, 256>>>();
    gemm_dual_deg_kernel<<<(NV + 127) / 128, 256>>>(verts, edges, w0w, w0b, w1w, w1b, out);
    scan1_kernel<<<NBLK_SCAN, SCAN_BLK>>>();
    scan23_kernel<<<nbV, 256>>>();
    fill_kernel<<<nbE, 256>>>(edges);
    gather_kernel<<<(NV + 31) / 32, 256>>>(out);
}